// round 12
// baseline (speedup 1.0000x reference)
#include <cuda_runtime.h>
#include <cuda_bf16.h>
#include <cstdint>

#define EPS_BN 1e-5f

// ===================== PTX helpers (sm_90 mainline; OK for sm_103 non-a) =====================
__device__ __forceinline__ uint32_t smem_to_u32(const void* p) {
    uint32_t a;
    asm("{ .reg .u64 t; cvta.to.shared.u64 t, %1; cvt.u32.u64 %0, t; }" : "=r"(a) : "l"(p));
    return a;
}
#define MBARRIER_INIT(addr, count) \
    asm volatile("mbarrier.init.shared.b64 [%0], %1;" :: "r"((uint32_t)(addr)), "r"((uint32_t)(count)) : "memory")
#define MBARRIER_EXPECT_TX(addr, tx) \
    asm volatile("mbarrier.arrive.expect_tx.shared.b64 _, [%0], %1;" :: "r"((uint32_t)(addr)), "r"((uint32_t)(tx)) : "memory")
#define MBARRIER_ARRIVE(addr) \
    asm volatile("mbarrier.arrive.shared.b64 _, [%0];" :: "r"((uint32_t)(addr)) : "memory")

#define MBARRIER_WAIT_PARITY(mbar_smem_addr, phase_parity) do { \
    uint32_t _mbar = (uint32_t)(mbar_smem_addr); \
    uint32_t _parity = (uint32_t)(phase_parity); \
    uint32_t _done; \
    asm volatile("{\n\t.reg .pred p;\n\t" \
        "mbarrier.try_wait.parity.acquire.cta.shared::cta.b64 p, [%1], %2;\n\t" \
        "selp.b32 %0, 1, 0, p;\n\t}" : "=r"(_done) : "r"(_mbar), "r"(_parity) : "memory"); \
    if (!_done) { \
        asm volatile("{\n\t.reg .pred P1;\n\t" \
            "WAIT_LOOP_%=:\n\t" \
            "mbarrier.try_wait.parity.acquire.cta.shared::cta.b64 P1, [%0], %1, 0x989680;\n\t" \
            "@P1 bra.uni WAIT_DONE_%=;\n\t" \
            "bra.uni WAIT_LOOP_%=;\n\t" \
            "WAIT_DONE_%=:\n\t}" :: "r"(_mbar), "r"(_parity) : "memory"); \
    } \
} while(0)

__device__ __forceinline__ void bulk_g2s(uint32_t dst, const void* src, uint32_t bytes, uint32_t mbar) {
    asm volatile("cp.async.bulk.shared::cta.global.mbarrier::complete_tx::bytes [%0], [%1], %2, [%3];"
        :: "r"(dst), "l"(src), "r"(bytes), "r"(mbar) : "memory");
}
__device__ __forceinline__ void cp16(uint32_t dst, const void* src) {
    asm volatile("cp.async.cg.shared.global [%0], [%1], 16;\n" :: "r"(dst), "l"(src));
}
#define CP_COMMIT() asm volatile("cp.async.commit_group;\n" ::: "memory")
#define CP_WAIT(N)  asm volatile("cp.async.wait_group %0;\n" :: "n"(N) : "memory")

#define LDSM_X4(r, addr) \
    asm volatile("ldmatrix.sync.aligned.m8n8.x4.shared.b16 {%0,%1,%2,%3}, [%4];" \
        : "=r"((r)[0]), "=r"((r)[1]), "=r"((r)[2]), "=r"((r)[3]) : "r"(addr))

#define MMA_S8(c, a0, a1, a2, a3, b0, b1) \
    asm volatile("mma.sync.aligned.m16n8k32.row.col.s32.s8.s8.s32 " \
        "{%0,%1,%2,%3}, {%4,%5,%6,%7}, {%8,%9}, {%0,%1,%2,%3};" \
        : "+r"((c)[0]), "+r"((c)[1]), "+r"((c)[2]), "+r"((c)[3]) \
        : "r"(a0), "r"(a1), "r"(a2), "r"(a3), "r"(b0), "r"(b1))

// Panel: 128 rows x 64 bytes = 8192 B, 16B-chunk swizzle within row.
__host__ __device__ __forceinline__ int swz_off(int r, int c) {     // r:0..127, c:0..63
    int chunk = (c >> 4) + (r >> 1);
    return r * 64 + ((chunk & 3) << 4) + (c & 15);
}

// ===================== static device workspace (panel layouts) =====================
__device__ __align__(256) int8_t g_A0[32768u * 896u];   // 256 mp x 14 kp panels
__device__ __align__(256) int8_t g_A1[32768u * 1024u];  // 256 x 16
__device__ __align__(256) int8_t g_A2[32768u * 1024u];
__device__ __align__(256) int8_t g_W1[1024u * 896u];    // 8 np x 14 kp
__device__ __align__(256) int8_t g_W2[1024u * 1024u];   // 8 x 16
__device__ __align__(256) int8_t g_W3[1024u * 1024u];
__device__ __align__(256) int8_t g_W4[16u * 1024u];     // plain row-major, rows 10..15 zero

// ===================== fused pack: ONE launch for all inputs =====================
__device__ __forceinline__ void pack_one(const float* __restrict__ src, int8_t* __restrict__ dst,
                                         int mp, int kp, int Kreal, int KPAN) {
    int8_t* d = dst + ((size_t)mp * KPAN + kp) * 8192;
    const float* s = src + (size_t)mp * 128 * Kreal + kp * 64;
    for (int i = threadIdx.x; i < 8192; i += 256) {
        int r = i >> 6, c = i & 63;
        int8_t v = 0;
        if (kp * 64 + c < Kreal) v = (s[(size_t)r * Kreal + c] >= 0.0f) ? (int8_t)1 : (int8_t)-1;
        d[swz_off(r, c)] = v;
    }
}

__global__ void pack_all(const float* __restrict__ x,  int8_t* __restrict__ a0,
                         const float* __restrict__ W1, int8_t* __restrict__ w1,
                         const float* __restrict__ W2, int8_t* __restrict__ w2,
                         const float* __restrict__ W3, int8_t* __restrict__ w3,
                         const float* __restrict__ W4, int8_t* __restrict__ w4) {
    int b = blockIdx.x;
    if (b < 3584)      { pack_one(x,  a0, b / 14,          b % 14,          784,  14); }
    else if (b < 3696) { b -= 3584; pack_one(W1, w1, b / 14, b % 14,        784,  14); }
    else if (b < 3824) { b -= 3696; pack_one(W2, w2, b >> 4, b & 15,        1024, 16); }
    else if (b < 3952) { b -= 3824; pack_one(W3, w3, b >> 4, b & 15,        1024, 16); }
    else {
        int r = b - 3952;
        int c = threadIdx.x * 4;
        for (int u = 0; u < 4; ++u) {
            int8_t v = 0;
            if (r < 10) v = (W4[(size_t)r * 1024 + c + u] >= 0.0f) ? (int8_t)1 : (int8_t)-1;
            w4[(size_t)r * 1024 + c + u] = v;
        }
    }
}

// ===================== GEMM: z=0 tensor CTAs (R6 verbatim), z=1 dp4a CTAs (clean) =====================
#define NSTAGE   4
#define STG_SZ   16384
#define SM_TOTAL (NSTAGE * STG_SZ)    // 65536
#define DP_PITCH 80                   // deswizzled row pitch (conflict-free: 5 units/row)

__global__ void __launch_bounds__(256, 2)
bgemm_split(const int8_t* __restrict__ A, const int8_t* __restrict__ W, int KPAN,
            const float* __restrict__ bias, const float* __restrict__ gamma,
            const float* __restrict__ beta, const float* __restrict__ mean,
            const float* __restrict__ var, int8_t* __restrict__ Aout) {
    extern __shared__ char smc[];
    __shared__ __align__(8) uint64_t mbars[2 * NSTAGE];
    __shared__ float s_scale[128];
    __shared__ float s_shift[128];

    const int t    = threadIdx.x;
    const int lane = t & 31;
    const int wid  = t >> 5;
    const int col0 = blockIdx.x * 128;
    const uint32_t smem_base = smem_to_u32(smc);
    const int NK = KPAN;

    if (t < 128) {
        int j = col0 + t;
        float sv = gamma[j] * rsqrtf(var[j] + EPS_BN);
        s_scale[t] = sv;
        s_shift[t] = sv * (bias[j] - mean[j]) + beta[j];
    }

    if (blockIdx.z == 0) {
        // ================= tensor path: M-tiles 0..127 (R6 code, proven) =================
        const int my = blockIdx.y;
        const uint32_t mb_full  = smem_to_u32(&mbars[0]);
        const uint32_t mb_empty = smem_to_u32(&mbars[NSTAGE]);
        const int warp_m = wid & 1;
        const int warp_n = wid >> 1;

        if (t == 0) {
#pragma unroll
            for (int s = 0; s < NSTAGE; ++s) {
                MBARRIER_INIT(mb_full + s * 8, 1);
                MBARRIER_INIT(mb_empty + s * 8, 8);
            }
        }
        __syncthreads();

        const int8_t* pA = A + (size_t)my * KPAN * 8192;
        const int8_t* pB = W + (size_t)blockIdx.x * KPAN * 8192;

#define PRODUCE(i) do {                                                        \
        int _s = (i) & 3;                                                      \
        MBARRIER_WAIT_PARITY(mb_empty + _s * 8, ((((i) >> 2) + 1) & 1));       \
        MBARRIER_EXPECT_TX(mb_full + _s * 8, STG_SZ);                          \
        uint32_t _d = smem_base + _s * STG_SZ;                                 \
        bulk_g2s(_d,        pA + (size_t)(i) * 8192, 8192, mb_full + _s * 8);  \
        bulk_g2s(_d + 8192, pB + (size_t)(i) * 8192, 8192, mb_full + _s * 8);  \
    } while (0)

        if (t == 0) {
            int np = NK < 3 ? NK : 3;
            for (int p = 0; p < np; ++p) PRODUCE(p);
        }

        int acc[4][4][4];
#pragma unroll
        for (int i = 0; i < 4; ++i)
#pragma unroll
            for (int j = 0; j < 4; ++j)
#pragma unroll
                for (int k = 0; k < 4; ++k) acc[i][j][k] = 0;

        const int r0a   = warp_m * 64 + (lane & 15);
        const int r0b   = warp_n * 32 + (lane & 15);
        const int klane = lane >> 4;
        const int rowtA = r0a * 64;
        const int rowtB = r0b * 64;
        const int csaA  = (klane + (r0a >> 1)) & 3;
        const int csaB  = (klane + (r0b >> 1)) & 3;

        for (int kt = 0; kt < NK; ++kt) {
            if (t == 0 && kt + 3 < NK) PRODUCE(kt + 3);
            const int s4 = kt & 3;
            MBARRIER_WAIT_PARITY(mb_full + s4 * 8, (kt >> 2) & 1);

            const uint32_t stA = smem_base + s4 * STG_SZ;
            const uint32_t stB = stA + 8192;
#pragma unroll
            for (int s = 0; s < 2; ++s) {
                uint32_t aAddr = stA + rowtA + ((((s << 1) + csaA) & 3) << 4);
                uint32_t bAddr = stB + rowtB + ((((s << 1) + csaB) & 3) << 4);
                uint32_t af[4][4], bf[2][4];
#pragma unroll
                for (int mf = 0; mf < 4; ++mf)
                    LDSM_X4(af[mf], aAddr + mf * 1024);
#pragma unroll
                for (int p = 0; p < 2; ++p)
                    LDSM_X4(bf[p], bAddr + p * 1024);
#pragma unroll
                for (int mf = 0; mf < 4; ++mf)
#pragma unroll
                    for (int nf = 0; nf < 4; ++nf)
                        MMA_S8(acc[mf][nf],
                               af[mf][0], af[mf][1], af[mf][2], af[mf][3],
                               bf[nf >> 1][nf & 1], bf[nf >> 1][(nf & 1) + 2]);
            }
            if (lane == 0) MBARRIER_ARRIVE(mb_empty + s4 * 8);
        }

        // epilogue: shuffle-gather to STG.128 (R6 verbatim)
        const int rbase = warp_m * 64 + (lane >> 2) + ((lane & 1) ? 8 : 0);
        const int cbase = warp_n * 32 + ((lane & 2) ? 16 : 0);
        const int gcol  = col0 + cbase;
        int8_t* pnl = Aout + ((size_t)my * 16 + (gcol >> 6)) * 8192;
        const int cloc = gcol & 63;

#pragma unroll
        for (int mf = 0; mf < 4; ++mf) {
            uint32_t w[4];
#pragma unroll
            for (int nf = 0; nf < 4; ++nf) {
                int lc = warp_n * 32 + nf * 8 + (lane & 3) * 2;
                float sc0 = s_scale[lc],     sh0 = s_shift[lc];
                float sc1 = s_scale[lc + 1], sh1 = s_shift[lc + 1];
                uint32_t b0 = (sc0 * (float)acc[mf][nf][0] + sh0 >= 0.0f) ? 0x01u : 0xFFu;
                uint32_t b1 = (sc1 * (float)acc[mf][nf][1] + sh1 >= 0.0f) ? 0x01u : 0xFFu;
                uint32_t b2 = (sc0 * (float)acc[mf][nf][2] + sh0 >= 0.0f) ? 0x01u : 0xFFu;
                uint32_t b3 = (sc1 * (float)acc[mf][nf][3] + sh1 >= 0.0f) ? 0x01u : 0xFFu;
                uint32_t my01 = b0 | (b1 << 8);
                uint32_t my23 = b2 | (b3 << 8);
                uint32_t o01 = __shfl_xor_sync(0xffffffffu, my01, 1);
                uint32_t o23 = __shfl_xor_sync(0xffffffffu, my23, 1);
                w[nf] = (lane & 1) ? (o23 | (my23 << 16)) : (my01 | (o01 << 16));
            }
            uint32_t p0 = __shfl_xor_sync(0xffffffffu, w[0], 2);
            uint32_t p1 = __shfl_xor_sync(0xffffffffu, w[1], 2);
            uint32_t p2 = __shfl_xor_sync(0xffffffffu, w[2], 2);
            uint32_t p3 = __shfl_xor_sync(0xffffffffu, w[3], 2);
            int4 v = (lane & 2) ? make_int4((int)p2, (int)w[2], (int)p3, (int)w[3])
                                : make_int4((int)w[0], (int)p0, (int)w[1], (int)p1);
            int r = rbase + mf * 16;
            *(int4*)(pnl + swz_off(r, cloc)) = v;
        }
#undef PRODUCE
    } else {
        // ===== dp4a path: M-tiles 128..255. Single-buffer sync staging, DESWIZZLED =====
        // smem: A [128][80] at 0, B [128][80] at 10240. No swizzle in compute loop.
        const int my = 128 + blockIdx.y;
        const int8_t* pA = A + (size_t)my * KPAN * 8192;
        const int8_t* pB = W + (size_t)blockIdx.x * KPAN * 8192;

        const int r0  = t & 31;            // rows r0, r0+32, r0+64, r0+96
        const int cg8 = t >> 5;            // cols cg8*16 .. +15
        const uint32_t smA = smem_base;
        const uint32_t smB = smem_base + 10240;

        int acc[4][16];
#pragma unroll
        for (int j = 0; j < 4; ++j)
#pragma unroll
            for (int c = 0; c < 16; ++c) acc[j][c] = 0;

        for (int kt = 0; kt < NK; ++kt) {
            __syncthreads();               // previous iteration's reads done
            // stage + deswizzle: 512 chunks each for A and B, 2 per thread per operand
#pragma unroll
            for (int l = 0; l < 2; ++l) {
                int idx = t + l * 256;     // 0..511
                int r = idx >> 2, ch = idx & 3;
                int srcoff = r * 64 + (((ch + (r >> 1)) & 3) << 4);  // swizzled source
                int dstoff = r * DP_PITCH + ch * 16;                 // plain dest
                cp16(smA + dstoff, pA + (size_t)kt * 8192 + srcoff);
                cp16(smB + dstoff, pB + (size_t)kt * 8192 + srcoff);
            }
            CP_COMMIT();
            CP_WAIT(0);
            __syncthreads();

            // compute: A rows 1-apart (conflict-free), B warp-uniform (broadcast)
#pragma unroll
            for (int ch = 0; ch < 4; ++ch) {
                int4 a[4];
#pragma unroll
                for (int j = 0; j < 4; ++j)
                    a[j] = *(const int4*)(smc + (r0 + 32 * j) * DP_PITCH + ch * 16);
#pragma unroll
                for (int c = 0; c < 16; ++c) {
                    int4 b = *(const int4*)(smc + 10240 + (cg8 * 16 + c) * DP_PITCH + ch * 16);
#pragma unroll
                    for (int j = 0; j < 4; ++j) {
                        int s = acc[j][c];
                        s = __dp4a(a[j].x, b.x, s);
                        s = __dp4a(a[j].y, b.y, s);
                        s = __dp4a(a[j].z, b.z, s);
                        s = __dp4a(a[j].w, b.w, s);
                        acc[j][c] = s;
                    }
                }
            }
        }

        // epilogue: BN + sign, 16 cols/row -> STG.128 into swizzled panel
        const int gcol = col0 + cg8 * 16;
        int8_t* pnl = Aout + ((size_t)my * 16 + (gcol >> 6)) * 8192;
        const int cloc = gcol & 63;
        float sc[16], sh[16];
#pragma unroll
        for (int c = 0; c < 16; ++c) { sc[c] = s_scale[cg8 * 16 + c]; sh[c] = s_shift[cg8 * 16 + c]; }
#pragma unroll
        for (int j = 0; j < 4; ++j) {
            uint32_t w[4];
#pragma unroll
            for (int q = 0; q < 4; ++q) {
                uint32_t acc4 = 0;
#pragma unroll
                for (int k = 0; k < 4; ++k) {
                    int c = q * 4 + k;
                    float y = sc[c] * (float)acc[j][c] + sh[c];
                    acc4 |= (y >= 0.0f ? 0x01u : 0xFFu) << (8 * k);
                }
                w[q] = acc4;
            }
            *(int4*)(pnl + swz_off(r0 + 32 * j, cloc)) =
                make_int4((int)w[0], (int)w[1], (int)w[2], (int)w[3]);
        }
    }
}

// ===================== layer 4 via mma: N=16 (10 real), A in panels =====================
__global__ void __launch_bounds__(256)
final_mma(const int8_t* __restrict__ A, const int8_t* __restrict__ W,
          const float* __restrict__ bias, const float* __restrict__ gamma,
          const float* __restrict__ beta, const float* __restrict__ mean,
          const float* __restrict__ var, float* __restrict__ out) {
    const int lane = threadIdx.x & 31;
    const int wid  = threadIdx.x >> 5;
    const int row0 = (blockIdx.x * 8 + wid) * 16;
    const int mp   = row0 >> 7;
    const int rl0  = row0 & 127;

    int acc[2][4];
#pragma unroll
    for (int i = 0; i < 2; ++i)
#pragma unroll
        for (int k = 0; k < 4; ++k) acc[i][k] = 0;

    const int r4 = lane >> 2;
    const int c4 = (lane & 3) * 4;

#pragma unroll 4
    for (int ks = 0; ks < 32; ++ks) {
        int kb = ks * 32;
        const int8_t* pnl = A + ((size_t)mp * 16 + (kb >> 6)) * 8192;
        int cb = kb & 63;
        uint32_t a0 = *(const uint32_t*)(pnl + swz_off(rl0 + r4,     cb + c4));
        uint32_t a1 = *(const uint32_t*)(pnl + swz_off(rl0 + r4 + 8, cb + c4));
        uint32_t a2 = *(const uint32_t*)(pnl + swz_off(rl0 + r4,     cb + 16 + c4));
        uint32_t a3 = *(const uint32_t*)(pnl + swz_off(rl0 + r4 + 8, cb + 16 + c4));
#pragma unroll
        for (int nt = 0; nt < 2; ++nt) {
            uint32_t b0 = *(const uint32_t*)(W + (size_t)(nt * 8 + r4) * 1024 + kb + c4);
            uint32_t b1 = *(const uint32_t*)(W + (size_t)(nt * 8 + r4) * 1024 + kb + 16 + c4);
            MMA_S8(acc[nt], a0, a1, a2, a3, b0, b1);
        }
    }

#pragma unroll
    for (int nt = 0; nt < 2; ++nt)
#pragma unroll
        for (int k = 0; k < 4; ++k) {
            int c = nt * 8 + (lane & 3) * 2 + (k & 1);
            int r = row0 + (lane >> 2) + (k >> 1) * 8;
            if (c < 10) {
                float sv = gamma[c] * rsqrtf(var[c] + EPS_BN);
                out[(size_t)r * 10 + c] =
                    sv * ((float)acc[nt][k] + bias[c] - mean[c]) + beta[c];
            }
        }
}

// ===================== launch =====================
extern "C" void kernel_launch(void* const* d_in, const int* in_sizes, int n_in,
                              void* d_out, int out_size) {
    const float* x  = (const float*)d_in[0];
    const float* W1 = (const float*)d_in[1];
    const float* b1 = (const float*)d_in[2];
    const float* g1 = (const float*)d_in[3];
    const float* be1= (const float*)d_in[4];
    const float* m1 = (const float*)d_in[5];
    const float* v1 = (const float*)d_in[6];
    const float* W2 = (const float*)d_in[7];
    const float* b2 = (const float*)d_in[8];
    const float* g2 = (const float*)d_in[9];
    const float* be2= (const float*)d_in[10];
    const float* m2 = (const float*)d_in[11];
    const float* v2 = (const float*)d_in[12];
    const float* W3 = (const float*)d_in[13];
    const float* b3 = (const float*)d_in[14];
    const float* g3 = (const float*)d_in[15];
    const float* be3= (const float*)d_in[16];
    const float* m3 = (const float*)d_in[17];
    const float* v3 = (const float*)d_in[18];
    const float* W4 = (const float*)d_in[19];
    const float* b4 = (const float*)d_in[20];
    const float* g4 = (const float*)d_in[21];
    const float* be4= (const float*)d_in[22];
    const float* m4 = (const float*)d_in[23];
    const float* v4 = (const float*)d_in[24];

    int8_t *a0, *a1, *a2, *w1, *w2, *w3, *w4;
    cudaGetSymbolAddress((void**)&a0, g_A0);
    cudaGetSymbolAddress((void**)&a1, g_A1);
    cudaGetSymbolAddress((void**)&a2, g_A2);
    cudaGetSymbolAddress((void**)&w1, g_W1);
    cudaGetSymbolAddress((void**)&w2, g_W2);
    cudaGetSymbolAddress((void**)&w3, g_W3);
    cudaGetSymbolAddress((void**)&w4, g_W4);

    const int M = 32768;

    pack_all<<<3968, 256>>>(x, a0, W1, w1, W2, w2, W3, w3, W4, w4);

    cudaFuncSetAttribute(bgemm_split, cudaFuncAttributeMaxDynamicSharedMemorySize, SM_TOTAL);

    dim3 grid(8, 128, 2);   // x = N tiles, y = M tiles within half, z = tensor/dp4a half

    bgemm_split<<<grid, 256, SM_TOTAL>>>(a0, w1, 14, b1, g1, be1, m1, v1, a1);
    bgemm_split<<<grid, 256, SM_TOTAL>>>(a1, w2, 16, b2, g2, be2, m2, v2, a2);
    bgemm_split<<<grid, 256, SM_TOTAL>>>(a2, w3, 16, b3, g3, be3, m3, v3, a1);

    final_mma<<<M / 128, 256>>>(a1, w4, b4, g4, be4, m4, v4, (float*)d_out);
}

// round 13
// speedup vs baseline: 1.1607x; 1.1607x over previous
#include <cuda_runtime.h>
#include <cuda_bf16.h>
#include <cstdint>

#define EPS_BN 1e-5f

// ===================== PTX helpers (sm_90 mainline; OK for sm_103 non-a) =====================
__device__ __forceinline__ uint32_t smem_to_u32(const void* p) {
    uint32_t a;
    asm("{ .reg .u64 t; cvta.to.shared.u64 t, %1; cvt.u32.u64 %0, t; }" : "=r"(a) : "l"(p));
    return a;
}
#define MBARRIER_INIT(addr, count) \
    asm volatile("mbarrier.init.shared.b64 [%0], %1;" :: "r"((uint32_t)(addr)), "r"((uint32_t)(count)) : "memory")
#define MBARRIER_EXPECT_TX(addr, tx) \
    asm volatile("mbarrier.arrive.expect_tx.shared.b64 _, [%0], %1;" :: "r"((uint32_t)(addr)), "r"((uint32_t)(tx)) : "memory")
#define MBARRIER_ARRIVE(addr) \
    asm volatile("mbarrier.arrive.shared.b64 _, [%0];" :: "r"((uint32_t)(addr)) : "memory")

#define MBARRIER_WAIT_PARITY(mbar_smem_addr, phase_parity) do { \
    uint32_t _mbar = (uint32_t)(mbar_smem_addr); \
    uint32_t _parity = (uint32_t)(phase_parity); \
    uint32_t _done; \
    asm volatile("{\n\t.reg .pred p;\n\t" \
        "mbarrier.try_wait.parity.acquire.cta.shared::cta.b64 p, [%1], %2;\n\t" \
        "selp.b32 %0, 1, 0, p;\n\t}" : "=r"(_done) : "r"(_mbar), "r"(_parity) : "memory"); \
    if (!_done) { \
        asm volatile("{\n\t.reg .pred P1;\n\t" \
            "WAIT_LOOP_%=:\n\t" \
            "mbarrier.try_wait.parity.acquire.cta.shared::cta.b64 P1, [%0], %1, 0x989680;\n\t" \
            "@P1 bra.uni WAIT_DONE_%=;\n\t" \
            "bra.uni WAIT_LOOP_%=;\n\t" \
            "WAIT_DONE_%=:\n\t}" :: "r"(_mbar), "r"(_parity) : "memory"); \
    } \
} while(0)

__device__ __forceinline__ void bulk_g2s(uint32_t dst, const void* src, uint32_t bytes, uint32_t mbar) {
    asm volatile("cp.async.bulk.shared::cta.global.mbarrier::complete_tx::bytes [%0], [%1], %2, [%3];"
        :: "r"(dst), "l"(src), "r"(bytes), "r"(mbar) : "memory");
}
__device__ __forceinline__ void cp16(uint32_t dst, const void* src) {
    asm volatile("cp.async.cg.shared.global [%0], [%1], 16;\n" :: "r"(dst), "l"(src));
}
#define CP_COMMIT() asm volatile("cp.async.commit_group;\n" ::: "memory")
#define CP_WAIT(N)  asm volatile("cp.async.wait_group %0;\n" :: "n"(N) : "memory")

#define LDSM_X4(r, addr) \
    asm volatile("ldmatrix.sync.aligned.m8n8.x4.shared.b16 {%0,%1,%2,%3}, [%4];" \
        : "=r"((r)[0]), "=r"((r)[1]), "=r"((r)[2]), "=r"((r)[3]) : "r"(addr))

#define MMA_S8(c, a0, a1, a2, a3, b0, b1) \
    asm volatile("mma.sync.aligned.m16n8k32.row.col.s32.s8.s8.s32 " \
        "{%0,%1,%2,%3}, {%4,%5,%6,%7}, {%8,%9}, {%0,%1,%2,%3};" \
        : "+r"((c)[0]), "+r"((c)[1]), "+r"((c)[2]), "+r"((c)[3]) \
        : "r"(a0), "r"(a1), "r"(a2), "r"(a3), "r"(b0), "r"(b1))

// Panel: 128 rows x 64 bytes = 8192 B, 16B-chunk swizzle within row.
__host__ __device__ __forceinline__ int swz_off(int r, int c) {     // r:0..127, c:0..63
    int chunk = (c >> 4) + (r >> 1);
    return r * 64 + ((chunk & 3) << 4) + (c & 15);
}

// ===================== static device workspace (panel layouts) =====================
__device__ __align__(256) int8_t g_A0[32768u * 896u];   // 256 mp x 14 kp panels
__device__ __align__(256) int8_t g_A1[32768u * 1024u];  // 256 x 16
__device__ __align__(256) int8_t g_A2[32768u * 1024u];
__device__ __align__(256) int8_t g_W1[1024u * 896u];    // 8 np x 14 kp
__device__ __align__(256) int8_t g_W2[1024u * 1024u];   // 8 x 16
__device__ __align__(256) int8_t g_W3[1024u * 1024u];
__device__ __align__(256) int8_t g_W4[16u * 1024u];     // plain row-major, rows 10..15 zero

// ===================== fused pack: ONE launch for all inputs =====================
__device__ __forceinline__ void pack_one(const float* __restrict__ src, int8_t* __restrict__ dst,
                                         int mp, int kp, int Kreal, int KPAN) {
    int8_t* d = dst + ((size_t)mp * KPAN + kp) * 8192;
    const float* s = src + (size_t)mp * 128 * Kreal + kp * 64;
    for (int i = threadIdx.x; i < 8192; i += 256) {
        int r = i >> 6, c = i & 63;
        int8_t v = 0;
        if (kp * 64 + c < Kreal) v = (s[(size_t)r * Kreal + c] >= 0.0f) ? (int8_t)1 : (int8_t)-1;
        d[swz_off(r, c)] = v;
    }
}

__global__ void pack_all(const float* __restrict__ x,  int8_t* __restrict__ a0,
                         const float* __restrict__ W1, int8_t* __restrict__ w1,
                         const float* __restrict__ W2, int8_t* __restrict__ w2,
                         const float* __restrict__ W3, int8_t* __restrict__ w3,
                         const float* __restrict__ W4, int8_t* __restrict__ w4) {
    int b = blockIdx.x;
    if (b < 3584)      { pack_one(x,  a0, b / 14,          b % 14,          784,  14); }
    else if (b < 3696) { b -= 3584; pack_one(W1, w1, b / 14, b % 14,        784,  14); }
    else if (b < 3824) { b -= 3696; pack_one(W2, w2, b >> 4, b & 15,        1024, 16); }
    else if (b < 3952) { b -= 3824; pack_one(W3, w3, b >> 4, b & 15,        1024, 16); }
    else {
        int r = b - 3952;
        int c = threadIdx.x * 4;
        for (int u = 0; u < 4; ++u) {
            int8_t v = 0;
            if (r < 10) v = (W4[(size_t)r * 1024 + c + u] >= 0.0f) ? (int8_t)1 : (int8_t)-1;
            w4[(size_t)r * 1024 + c + u] = v;
        }
    }
}

// ===================== GEMM: interleaved tensor / dp4a CTAs over 256 M-tiles =====================
// Type by (blockIdx.y & 15) < 11  ->  176 tensor tiles : 80 dp4a tiles (rate-balanced 1.80 : 3.77),
// interleaved so every scheduling wave holds both types (true pipe overlap).
#define NSTAGE   4
#define STG_SZ   16384
#define SM_TOTAL (NSTAGE * STG_SZ)    // 65536
#define DP_PITCH 80                   // deswizzled row pitch (conflict-free: 5 units/row)

__global__ void __launch_bounds__(256, 2)
bgemm_split(const int8_t* __restrict__ A, const int8_t* __restrict__ W, int KPAN,
            const float* __restrict__ bias, const float* __restrict__ gamma,
            const float* __restrict__ beta, const float* __restrict__ mean,
            const float* __restrict__ var, int8_t* __restrict__ Aout) {
    extern __shared__ char smc[];
    __shared__ __align__(8) uint64_t mbars[2 * NSTAGE];
    __shared__ float s_scale[128];
    __shared__ float s_shift[128];

    const int t    = threadIdx.x;
    const int lane = t & 31;
    const int wid  = t >> 5;
    const int col0 = blockIdx.x * 128;
    const uint32_t smem_base = smem_to_u32(smc);
    const int NK = KPAN;
    const int my = blockIdx.y;

    if (t < 128) {
        int j = col0 + t;
        float sv = gamma[j] * rsqrtf(var[j] + EPS_BN);
        s_scale[t] = sv;
        s_shift[t] = sv * (bias[j] - mean[j]) + beta[j];
    }

    if ((blockIdx.y & 15) < 11) {
        // ================= tensor path (R6 code, proven) =================
        const uint32_t mb_full  = smem_to_u32(&mbars[0]);
        const uint32_t mb_empty = smem_to_u32(&mbars[NSTAGE]);
        const int warp_m = wid & 1;
        const int warp_n = wid >> 1;

        if (t == 0) {
#pragma unroll
            for (int s = 0; s < NSTAGE; ++s) {
                MBARRIER_INIT(mb_full + s * 8, 1);
                MBARRIER_INIT(mb_empty + s * 8, 8);
            }
        }
        __syncthreads();

        const int8_t* pA = A + (size_t)my * KPAN * 8192;
        const int8_t* pB = W + (size_t)blockIdx.x * KPAN * 8192;

#define PRODUCE(i) do {                                                        \
        int _s = (i) & 3;                                                      \
        MBARRIER_WAIT_PARITY(mb_empty + _s * 8, ((((i) >> 2) + 1) & 1));       \
        MBARRIER_EXPECT_TX(mb_full + _s * 8, STG_SZ);                          \
        uint32_t _d = smem_base + _s * STG_SZ;                                 \
        bulk_g2s(_d,        pA + (size_t)(i) * 8192, 8192, mb_full + _s * 8);  \
        bulk_g2s(_d + 8192, pB + (size_t)(i) * 8192, 8192, mb_full + _s * 8);  \
    } while (0)

        if (t == 0) {
            int np = NK < 3 ? NK : 3;
            for (int p = 0; p < np; ++p) PRODUCE(p);
        }

        int acc[4][4][4];
#pragma unroll
        for (int i = 0; i < 4; ++i)
#pragma unroll
            for (int j = 0; j < 4; ++j)
#pragma unroll
                for (int k = 0; k < 4; ++k) acc[i][j][k] = 0;

        const int r0a   = warp_m * 64 + (lane & 15);
        const int r0b   = warp_n * 32 + (lane & 15);
        const int klane = lane >> 4;
        const int rowtA = r0a * 64;
        const int rowtB = r0b * 64;
        const int csaA  = (klane + (r0a >> 1)) & 3;
        const int csaB  = (klane + (r0b >> 1)) & 3;

        for (int kt = 0; kt < NK; ++kt) {
            if (t == 0 && kt + 3 < NK) PRODUCE(kt + 3);
            const int s4 = kt & 3;
            MBARRIER_WAIT_PARITY(mb_full + s4 * 8, (kt >> 2) & 1);

            const uint32_t stA = smem_base + s4 * STG_SZ;
            const uint32_t stB = stA + 8192;
#pragma unroll
            for (int s = 0; s < 2; ++s) {
                uint32_t aAddr = stA + rowtA + ((((s << 1) + csaA) & 3) << 4);
                uint32_t bAddr = stB + rowtB + ((((s << 1) + csaB) & 3) << 4);
                uint32_t af[4][4], bf[2][4];
#pragma unroll
                for (int mf = 0; mf < 4; ++mf)
                    LDSM_X4(af[mf], aAddr + mf * 1024);
#pragma unroll
                for (int p = 0; p < 2; ++p)
                    LDSM_X4(bf[p], bAddr + p * 1024);
#pragma unroll
                for (int mf = 0; mf < 4; ++mf)
#pragma unroll
                    for (int nf = 0; nf < 4; ++nf)
                        MMA_S8(acc[mf][nf],
                               af[mf][0], af[mf][1], af[mf][2], af[mf][3],
                               bf[nf >> 1][nf & 1], bf[nf >> 1][(nf & 1) + 2]);
            }
            if (lane == 0) MBARRIER_ARRIVE(mb_empty + s4 * 8);
        }

        // epilogue: shuffle-gather to STG.128 (R6 verbatim)
        const int rbase = warp_m * 64 + (lane >> 2) + ((lane & 1) ? 8 : 0);
        const int cbase = warp_n * 32 + ((lane & 2) ? 16 : 0);
        const int gcol  = col0 + cbase;
        int8_t* pnl = Aout + ((size_t)my * 16 + (gcol >> 6)) * 8192;
        const int cloc = gcol & 63;

#pragma unroll
        for (int mf = 0; mf < 4; ++mf) {
            uint32_t w[4];
#pragma unroll
            for (int nf = 0; nf < 4; ++nf) {
                int lc = warp_n * 32 + nf * 8 + (lane & 3) * 2;
                float sc0 = s_scale[lc],     sh0 = s_shift[lc];
                float sc1 = s_scale[lc + 1], sh1 = s_shift[lc + 1];
                uint32_t b0 = (sc0 * (float)acc[mf][nf][0] + sh0 >= 0.0f) ? 0x01u : 0xFFu;
                uint32_t b1 = (sc1 * (float)acc[mf][nf][1] + sh1 >= 0.0f) ? 0x01u : 0xFFu;
                uint32_t b2 = (sc0 * (float)acc[mf][nf][2] + sh0 >= 0.0f) ? 0x01u : 0xFFu;
                uint32_t b3 = (sc1 * (float)acc[mf][nf][3] + sh1 >= 0.0f) ? 0x01u : 0xFFu;
                uint32_t my01 = b0 | (b1 << 8);
                uint32_t my23 = b2 | (b3 << 8);
                uint32_t o01 = __shfl_xor_sync(0xffffffffu, my01, 1);
                uint32_t o23 = __shfl_xor_sync(0xffffffffu, my23, 1);
                w[nf] = (lane & 1) ? (o23 | (my23 << 16)) : (my01 | (o01 << 16));
            }
            uint32_t p0 = __shfl_xor_sync(0xffffffffu, w[0], 2);
            uint32_t p1 = __shfl_xor_sync(0xffffffffu, w[1], 2);
            uint32_t p2 = __shfl_xor_sync(0xffffffffu, w[2], 2);
            uint32_t p3 = __shfl_xor_sync(0xffffffffu, w[3], 2);
            int4 v = (lane & 2) ? make_int4((int)p2, (int)w[2], (int)p3, (int)w[3])
                                : make_int4((int)w[0], (int)p0, (int)w[1], (int)p1);
            int r = rbase + mf * 16;
            *(int4*)(pnl + swz_off(r, cloc)) = v;
        }
#undef PRODUCE
    } else {
        // ===== dp4a path (R12 code, proven): single-buffer sync staging, DESWIZZLED =====
        const int8_t* pA = A + (size_t)my * KPAN * 8192;
        const int8_t* pB = W + (size_t)blockIdx.x * KPAN * 8192;

        const int r0  = t & 31;            // rows r0, r0+32, r0+64, r0+96
        const int cg8 = t >> 5;            // cols cg8*16 .. +15
        const uint32_t smA = smem_base;
        const uint32_t smB = smem_base + 10240;

        int acc[4][16];
#pragma unroll
        for (int j = 0; j < 4; ++j)
#pragma unroll
            for (int c = 0; c < 16; ++c) acc[j][c] = 0;

        for (int kt = 0; kt < NK; ++kt) {
            __syncthreads();               // previous iteration's reads done
#pragma unroll
            for (int l = 0; l < 2; ++l) {
                int idx = t + l * 256;     // 0..511
                int r = idx >> 2, ch = idx & 3;
                int srcoff = r * 64 + (((ch + (r >> 1)) & 3) << 4);  // swizzled source
                int dstoff = r * DP_PITCH + ch * 16;                 // plain dest
                cp16(smA + dstoff, pA + (size_t)kt * 8192 + srcoff);
                cp16(smB + dstoff, pB + (size_t)kt * 8192 + srcoff);
            }
            CP_COMMIT();
            CP_WAIT(0);
            __syncthreads();

#pragma unroll
            for (int ch = 0; ch < 4; ++ch) {
                int4 a[4];
#pragma unroll
                for (int j = 0; j < 4; ++j)
                    a[j] = *(const int4*)(smc + (r0 + 32 * j) * DP_PITCH + ch * 16);
#pragma unroll
                for (int c = 0; c < 16; ++c) {
                    int4 b = *(const int4*)(smc + 10240 + (cg8 * 16 + c) * DP_PITCH + ch * 16);
#pragma unroll
                    for (int j = 0; j < 4; ++j) {
                        int s = acc[j][c];
                        s = __dp4a(a[j].x, b.x, s);
                        s = __dp4a(a[j].y, b.y, s);
                        s = __dp4a(a[j].z, b.z, s);
                        s = __dp4a(a[j].w, b.w, s);
                        acc[j][c] = s;
                    }
                }
            }
        }

        // epilogue: BN + sign, 16 cols/row -> STG.128 into swizzled panel
        const int gcol = col0 + cg8 * 16;
        int8_t* pnl = Aout + ((size_t)my * 16 + (gcol >> 6)) * 8192;
        const int cloc = gcol & 63;
        float sc[16], sh[16];
#pragma unroll
        for (int c = 0; c < 16; ++c) { sc[c] = s_scale[cg8 * 16 + c]; sh[c] = s_shift[cg8 * 16 + c]; }
#pragma unroll
        for (int j = 0; j < 4; ++j) {
            uint32_t w[4];
#pragma unroll
            for (int q = 0; q < 4; ++q) {
                uint32_t acc4 = 0;
#pragma unroll
                for (int k = 0; k < 4; ++k) {
                    int c = q * 4 + k;
                    float y = sc[c] * (float)acc[j][c] + sh[c];
                    acc4 |= (y >= 0.0f ? 0x01u : 0xFFu) << (8 * k);
                }
                w[q] = acc4;
            }
            *(int4*)(pnl + swz_off(r0 + 32 * j, cloc)) =
                make_int4((int)w[0], (int)w[1], (int)w[2], (int)w[3]);
        }
    }
}

// ===================== layer 4 via mma: N=16 (10 real), A in panels =====================
__global__ void __launch_bounds__(256)
final_mma(const int8_t* __restrict__ A, const int8_t* __restrict__ W,
          const float* __restrict__ bias, const float* __restrict__ gamma,
          const float* __restrict__ beta, const float* __restrict__ mean,
          const float* __restrict__ var, float* __restrict__ out) {
    const int lane = threadIdx.x & 31;
    const int wid  = threadIdx.x >> 5;
    const int row0 = (blockIdx.x * 8 + wid) * 16;
    const int mp   = row0 >> 7;
    const int rl0  = row0 & 127;

    int acc[2][4];
#pragma unroll
    for (int i = 0; i < 2; ++i)
#pragma unroll
        for (int k = 0; k < 4; ++k) acc[i][k] = 0;

    const int r4 = lane >> 2;
    const int c4 = (lane & 3) * 4;

#pragma unroll 4
    for (int ks = 0; ks < 32; ++ks) {
        int kb = ks * 32;
        const int8_t* pnl = A + ((size_t)mp * 16 + (kb >> 6)) * 8192;
        int cb = kb & 63;
        uint32_t a0 = *(const uint32_t*)(pnl + swz_off(rl0 + r4,     cb + c4));
        uint32_t a1 = *(const uint32_t*)(pnl + swz_off(rl0 + r4 + 8, cb + c4));
        uint32_t a2 = *(const uint32_t*)(pnl + swz_off(rl0 + r4,     cb + 16 + c4));
        uint32_t a3 = *(const uint32_t*)(pnl + swz_off(rl0 + r4 + 8, cb + 16 + c4));
#pragma unroll
        for (int nt = 0; nt < 2; ++nt) {
            uint32_t b0 = *(const uint32_t*)(W + (size_t)(nt * 8 + r4) * 1024 + kb + c4);
            uint32_t b1 = *(const uint32_t*)(W + (size_t)(nt * 8 + r4) * 1024 + kb + 16 + c4);
            MMA_S8(acc[nt], a0, a1, a2, a3, b0, b1);
        }
    }

#pragma unroll
    for (int nt = 0; nt < 2; ++nt)
#pragma unroll
        for (int k = 0; k < 4; ++k) {
            int c = nt * 8 + (lane & 3) * 2 + (k & 1);
            int r = row0 + (lane >> 2) + (k >> 1) * 8;
            if (c < 10) {
                float sv = gamma[c] * rsqrtf(var[c] + EPS_BN);
                out[(size_t)r * 10 + c] =
                    sv * ((float)acc[nt][k] + bias[c] - mean[c]) + beta[c];
            }
        }
}

// ===================== launch =====================
extern "C" void kernel_launch(void* const* d_in, const int* in_sizes, int n_in,
                              void* d_out, int out_size) {
    const float* x  = (const float*)d_in[0];
    const float* W1 = (const float*)d_in[1];
    const float* b1 = (const float*)d_in[2];
    const float* g1 = (const float*)d_in[3];
    const float* be1= (const float*)d_in[4];
    const float* m1 = (const float*)d_in[5];
    const float* v1 = (const float*)d_in[6];
    const float* W2 = (const float*)d_in[7];
    const float* b2 = (const float*)d_in[8];
    const float* g2 = (const float*)d_in[9];
    const float* be2= (const float*)d_in[10];
    const float* m2 = (const float*)d_in[11];
    const float* v2 = (const float*)d_in[12];
    const float* W3 = (const float*)d_in[13];
    const float* b3 = (const float*)d_in[14];
    const float* g3 = (const float*)d_in[15];
    const float* be3= (const float*)d_in[16];
    const float* m3 = (const float*)d_in[17];
    const float* v3 = (const float*)d_in[18];
    const float* W4 = (const float*)d_in[19];
    const float* b4 = (const float*)d_in[20];
    const float* g4 = (const float*)d_in[21];
    const float* be4= (const float*)d_in[22];
    const float* m4 = (const float*)d_in[23];
    const float* v4 = (const float*)d_in[24];

    int8_t *a0, *a1, *a2, *w1, *w2, *w3, *w4;
    cudaGetSymbolAddress((void**)&a0, g_A0);
    cudaGetSymbolAddress((void**)&a1, g_A1);
    cudaGetSymbolAddress((void**)&a2, g_A2);
    cudaGetSymbolAddress((void**)&w1, g_W1);
    cudaGetSymbolAddress((void**)&w2, g_W2);
    cudaGetSymbolAddress((void**)&w3, g_W3);
    cudaGetSymbolAddress((void**)&w4, g_W4);

    const int M = 32768;

    pack_all<<<3968, 256>>>(x, a0, W1, w1, W2, w2, W3, w3, W4, w4);

    cudaFuncSetAttribute(bgemm_split, cudaFuncAttributeMaxDynamicSharedMemorySize, SM_TOTAL);

    dim3 grid(8, 256);   // x = N tiles, y = M tiles (type interleaved 11:5 by y & 15)

    bgemm_split<<<grid, 256, SM_TOTAL>>>(a0, w1, 14, b1, g1, be1, m1, v1, a1);
    bgemm_split<<<grid, 256, SM_TOTAL>>>(a1, w2, 16, b2, g2, be2, m2, v2, a2);
    bgemm_split<<<grid, 256, SM_TOTAL>>>(a2, w3, 16, b3, g3, be3, m3, v3, a1);

    final_mma<<<M / 128, 256>>>(a1, w4, b4, g4, be4, m4, v4, (float*)d_out);
}

// round 14
// speedup vs baseline: 1.1618x; 1.0009x over previous
#include <cuda_runtime.h>
#include <cuda_bf16.h>
#include <cstdint>

#define EPS_BN 1e-5f

// ===================== PTX helpers (sm_90 mainline; OK for sm_103 non-a) =====================
__device__ __forceinline__ uint32_t smem_to_u32(const void* p) {
    uint32_t a;
    asm("{ .reg .u64 t; cvta.to.shared.u64 t, %1; cvt.u32.u64 %0, t; }" : "=r"(a) : "l"(p));
    return a;
}
#define MBARRIER_INIT(addr, count) \
    asm volatile("mbarrier.init.shared.b64 [%0], %1;" :: "r"((uint32_t)(addr)), "r"((uint32_t)(count)) : "memory")
#define MBARRIER_EXPECT_TX(addr, tx) \
    asm volatile("mbarrier.arrive.expect_tx.shared.b64 _, [%0], %1;" :: "r"((uint32_t)(addr)), "r"((uint32_t)(tx)) : "memory")
#define MBARRIER_ARRIVE(addr) \
    asm volatile("mbarrier.arrive.shared.b64 _, [%0];" :: "r"((uint32_t)(addr)) : "memory")

#define MBARRIER_WAIT_PARITY(mbar_smem_addr, phase_parity) do { \
    uint32_t _mbar = (uint32_t)(mbar_smem_addr); \
    uint32_t _parity = (uint32_t)(phase_parity); \
    uint32_t _done; \
    asm volatile("{\n\t.reg .pred p;\n\t" \
        "mbarrier.try_wait.parity.acquire.cta.shared::cta.b64 p, [%1], %2;\n\t" \
        "selp.b32 %0, 1, 0, p;\n\t}" : "=r"(_done) : "r"(_mbar), "r"(_parity) : "memory"); \
    if (!_done) { \
        asm volatile("{\n\t.reg .pred P1;\n\t" \
            "WAIT_LOOP_%=:\n\t" \
            "mbarrier.try_wait.parity.acquire.cta.shared::cta.b64 P1, [%0], %1, 0x989680;\n\t" \
            "@P1 bra.uni WAIT_DONE_%=;\n\t" \
            "bra.uni WAIT_LOOP_%=;\n\t" \
            "WAIT_DONE_%=:\n\t}" :: "r"(_mbar), "r"(_parity) : "memory"); \
    } \
} while(0)

__device__ __forceinline__ void bulk_g2s(uint32_t dst, const void* src, uint32_t bytes, uint32_t mbar) {
    asm volatile("cp.async.bulk.shared::cta.global.mbarrier::complete_tx::bytes [%0], [%1], %2, [%3];"
        :: "r"(dst), "l"(src), "r"(bytes), "r"(mbar) : "memory");
}
__device__ __forceinline__ void cp16(uint32_t dst, const void* src) {
    asm volatile("cp.async.cg.shared.global [%0], [%1], 16;\n" :: "r"(dst), "l"(src));
}
#define CP_COMMIT() asm volatile("cp.async.commit_group;\n" ::: "memory")
#define CP_WAIT(N)  asm volatile("cp.async.wait_group %0;\n" :: "n"(N) : "memory")

#define LDSM_X4(r, addr) \
    asm volatile("ldmatrix.sync.aligned.m8n8.x4.shared.b16 {%0,%1,%2,%3}, [%4];" \
        : "=r"((r)[0]), "=r"((r)[1]), "=r"((r)[2]), "=r"((r)[3]) : "r"(addr))

#define MMA_S8(c, a0, a1, a2, a3, b0, b1) \
    asm volatile("mma.sync.aligned.m16n8k32.row.col.s32.s8.s8.s32 " \
        "{%0,%1,%2,%3}, {%4,%5,%6,%7}, {%8,%9}, {%0,%1,%2,%3};" \
        : "+r"((c)[0]), "+r"((c)[1]), "+r"((c)[2]), "+r"((c)[3]) \
        : "r"(a0), "r"(a1), "r"(a2), "r"(a3), "r"(b0), "r"(b1))

// Panel: 128 rows x 64 bytes = 8192 B, 16B-chunk swizzle within row.
__host__ __device__ __forceinline__ int swz_off(int r, int c) {     // r:0..127, c:0..63
    int chunk = (c >> 4) + (r >> 1);
    return r * 64 + ((chunk & 3) << 4) + (c & 15);
}

// ===================== static device workspace (panel layouts) =====================
__device__ __align__(256) int8_t g_A0[32768u * 896u];   // 256 mp x 14 kp panels
__device__ __align__(256) int8_t g_A1[32768u * 1024u];  // 256 x 16
__device__ __align__(256) int8_t g_A2[32768u * 1024u];
__device__ __align__(256) int8_t g_W1[1024u * 896u];    // 8 np x 14 kp
__device__ __align__(256) int8_t g_W2[1024u * 1024u];   // 8 x 16
__device__ __align__(256) int8_t g_W3[1024u * 1024u];
__device__ __align__(256) int8_t g_W4[16u * 1024u];     // plain row-major, rows 10..15 zero

// ===================== fused pack: ONE launch for all inputs =====================
__device__ __forceinline__ void pack_one(const float* __restrict__ src, int8_t* __restrict__ dst,
                                         int mp, int kp, int Kreal, int KPAN) {
    int8_t* d = dst + ((size_t)mp * KPAN + kp) * 8192;
    const float* s = src + (size_t)mp * 128 * Kreal + kp * 64;
    for (int i = threadIdx.x; i < 8192; i += 256) {
        int r = i >> 6, c = i & 63;
        int8_t v = 0;
        if (kp * 64 + c < Kreal) v = (s[(size_t)r * Kreal + c] >= 0.0f) ? (int8_t)1 : (int8_t)-1;
        d[swz_off(r, c)] = v;
    }
}

__global__ void pack_all(const float* __restrict__ x,  int8_t* __restrict__ a0,
                         const float* __restrict__ W1, int8_t* __restrict__ w1,
                         const float* __restrict__ W2, int8_t* __restrict__ w2,
                         const float* __restrict__ W3, int8_t* __restrict__ w3,
                         const float* __restrict__ W4, int8_t* __restrict__ w4) {
    int b = blockIdx.x;
    if (b < 3584)      { pack_one(x,  a0, b / 14,          b % 14,          784,  14); }
    else if (b < 3696) { b -= 3584; pack_one(W1, w1, b / 14, b % 14,        784,  14); }
    else if (b < 3824) { b -= 3696; pack_one(W2, w2, b >> 4, b & 15,        1024, 16); }
    else if (b < 3952) { b -= 3824; pack_one(W3, w3, b >> 4, b & 15,        1024, 16); }
    else {
        int r = b - 3952;
        int c = threadIdx.x * 4;
        for (int u = 0; u < 4; ++u) {
            int8_t v = 0;
            if (r < 10) v = (W4[(size_t)r * 1024 + c + u] >= 0.0f) ? (int8_t)1 : (int8_t)-1;
            w4[(size_t)r * 1024 + c + u] = v;
        }
    }
}

// ===================== GEMM: scattered tensor / dp4a CTA types over linear bid =====================
// Type from linear bid (bid = x + 8y): dp4a iff (bid%16) % 3 == 2 -> {2,5,8,11,14} = 5/16.
// Same-type runs length <= 2 in scheduling order -> every wave mixes both types on most SMs.
#define NSTAGE   4
#define STG_SZ   16384
#define SM_TOTAL (NSTAGE * STG_SZ)    // 65536
#define DP_PITCH 80                   // deswizzled row pitch (conflict-free: 5 units/row)

__global__ void __launch_bounds__(256, 2)
bgemm_split(const int8_t* __restrict__ A, const int8_t* __restrict__ W, int KPAN,
            const float* __restrict__ bias, const float* __restrict__ gamma,
            const float* __restrict__ beta, const float* __restrict__ mean,
            const float* __restrict__ var, int8_t* __restrict__ Aout) {
    extern __shared__ char smc[];
    __shared__ __align__(8) uint64_t mbars[2 * NSTAGE];
    __shared__ float s_scale[128];
    __shared__ float s_shift[128];

    const int t    = threadIdx.x;
    const int lane = t & 31;
    const int wid  = t >> 5;
    const int col0 = blockIdx.x * 128;
    const uint32_t smem_base = smem_to_u32(smc);
    const int NK = KPAN;
    const int my = blockIdx.y;

    if (t < 128) {
        int j = col0 + t;
        float sv = gamma[j] * rsqrtf(var[j] + EPS_BN);
        s_scale[t] = sv;
        s_shift[t] = sv * (bias[j] - mean[j]) + beta[j];
    }

    const int bid16 = (blockIdx.x + blockIdx.y * 8) & 15;
    if ((bid16 % 3) != 2) {
        // ================= tensor path (R6 code, proven) =================
        const uint32_t mb_full  = smem_to_u32(&mbars[0]);
        const uint32_t mb_empty = smem_to_u32(&mbars[NSTAGE]);
        const int warp_m = wid & 1;
        const int warp_n = wid >> 1;

        if (t == 0) {
#pragma unroll
            for (int s = 0; s < NSTAGE; ++s) {
                MBARRIER_INIT(mb_full + s * 8, 1);
                MBARRIER_INIT(mb_empty + s * 8, 8);
            }
        }
        __syncthreads();

        const int8_t* pA = A + (size_t)my * KPAN * 8192;
        const int8_t* pB = W + (size_t)blockIdx.x * KPAN * 8192;

#define PRODUCE(i) do {                                                        \
        int _s = (i) & 3;                                                      \
        MBARRIER_WAIT_PARITY(mb_empty + _s * 8, ((((i) >> 2) + 1) & 1));       \
        MBARRIER_EXPECT_TX(mb_full + _s * 8, STG_SZ);                          \
        uint32_t _d = smem_base + _s * STG_SZ;                                 \
        bulk_g2s(_d,        pA + (size_t)(i) * 8192, 8192, mb_full + _s * 8);  \
        bulk_g2s(_d + 8192, pB + (size_t)(i) * 8192, 8192, mb_full + _s * 8);  \
    } while (0)

        if (t == 0) {
            int np = NK < 3 ? NK : 3;
            for (int p = 0; p < np; ++p) PRODUCE(p);
        }

        int acc[4][4][4];
#pragma unroll
        for (int i = 0; i < 4; ++i)
#pragma unroll
            for (int j = 0; j < 4; ++j)
#pragma unroll
                for (int k = 0; k < 4; ++k) acc[i][j][k] = 0;

        const int r0a   = warp_m * 64 + (lane & 15);
        const int r0b   = warp_n * 32 + (lane & 15);
        const int klane = lane >> 4;
        const int rowtA = r0a * 64;
        const int rowtB = r0b * 64;
        const int csaA  = (klane + (r0a >> 1)) & 3;
        const int csaB  = (klane + (r0b >> 1)) & 3;

        for (int kt = 0; kt < NK; ++kt) {
            if (t == 0 && kt + 3 < NK) PRODUCE(kt + 3);
            const int s4 = kt & 3;
            MBARRIER_WAIT_PARITY(mb_full + s4 * 8, (kt >> 2) & 1);

            const uint32_t stA = smem_base + s4 * STG_SZ;
            const uint32_t stB = stA + 8192;
#pragma unroll
            for (int s = 0; s < 2; ++s) {
                uint32_t aAddr = stA + rowtA + ((((s << 1) + csaA) & 3) << 4);
                uint32_t bAddr = stB + rowtB + ((((s << 1) + csaB) & 3) << 4);
                uint32_t af[4][4], bf[2][4];
#pragma unroll
                for (int mf = 0; mf < 4; ++mf)
                    LDSM_X4(af[mf], aAddr + mf * 1024);
#pragma unroll
                for (int p = 0; p < 2; ++p)
                    LDSM_X4(bf[p], bAddr + p * 1024);
#pragma unroll
                for (int mf = 0; mf < 4; ++mf)
#pragma unroll
                    for (int nf = 0; nf < 4; ++nf)
                        MMA_S8(acc[mf][nf],
                               af[mf][0], af[mf][1], af[mf][2], af[mf][3],
                               bf[nf >> 1][nf & 1], bf[nf >> 1][(nf & 1) + 2]);
            }
            if (lane == 0) MBARRIER_ARRIVE(mb_empty + s4 * 8);
        }

        // epilogue: shuffle-gather to STG.128 (R6 verbatim)
        const int rbase = warp_m * 64 + (lane >> 2) + ((lane & 1) ? 8 : 0);
        const int cbase = warp_n * 32 + ((lane & 2) ? 16 : 0);
        const int gcol  = col0 + cbase;
        int8_t* pnl = Aout + ((size_t)my * 16 + (gcol >> 6)) * 8192;
        const int cloc = gcol & 63;

#pragma unroll
        for (int mf = 0; mf < 4; ++mf) {
            uint32_t w[4];
#pragma unroll
            for (int nf = 0; nf < 4; ++nf) {
                int lc = warp_n * 32 + nf * 8 + (lane & 3) * 2;
                float sc0 = s_scale[lc],     sh0 = s_shift[lc];
                float sc1 = s_scale[lc + 1], sh1 = s_shift[lc + 1];
                uint32_t b0 = (sc0 * (float)acc[mf][nf][0] + sh0 >= 0.0f) ? 0x01u : 0xFFu;
                uint32_t b1 = (sc1 * (float)acc[mf][nf][1] + sh1 >= 0.0f) ? 0x01u : 0xFFu;
                uint32_t b2 = (sc0 * (float)acc[mf][nf][2] + sh0 >= 0.0f) ? 0x01u : 0xFFu;
                uint32_t b3 = (sc1 * (float)acc[mf][nf][3] + sh1 >= 0.0f) ? 0x01u : 0xFFu;
                uint32_t my01 = b0 | (b1 << 8);
                uint32_t my23 = b2 | (b3 << 8);
                uint32_t o01 = __shfl_xor_sync(0xffffffffu, my01, 1);
                uint32_t o23 = __shfl_xor_sync(0xffffffffu, my23, 1);
                w[nf] = (lane & 1) ? (o23 | (my23 << 16)) : (my01 | (o01 << 16));
            }
            uint32_t p0 = __shfl_xor_sync(0xffffffffu, w[0], 2);
            uint32_t p1 = __shfl_xor_sync(0xffffffffu, w[1], 2);
            uint32_t p2 = __shfl_xor_sync(0xffffffffu, w[2], 2);
            uint32_t p3 = __shfl_xor_sync(0xffffffffu, w[3], 2);
            int4 v = (lane & 2) ? make_int4((int)p2, (int)w[2], (int)p3, (int)w[3])
                                : make_int4((int)w[0], (int)p0, (int)w[1], (int)p1);
            int r = rbase + mf * 16;
            *(int4*)(pnl + swz_off(r, cloc)) = v;
        }
#undef PRODUCE
    } else {
        // ===== dp4a path (R12 code, proven): single-buffer sync staging, DESWIZZLED =====
        const int8_t* pA = A + (size_t)my * KPAN * 8192;
        const int8_t* pB = W + (size_t)blockIdx.x * KPAN * 8192;

        const int r0  = t & 31;            // rows r0, r0+32, r0+64, r0+96
        const int cg8 = t >> 5;            // cols cg8*16 .. +15
        const uint32_t smA = smem_base;
        const uint32_t smB = smem_base + 10240;

        int acc[4][16];
#pragma unroll
        for (int j = 0; j < 4; ++j)
#pragma unroll
            for (int c = 0; c < 16; ++c) acc[j][c] = 0;

        for (int kt = 0; kt < NK; ++kt) {
            __syncthreads();               // previous iteration's reads done
#pragma unroll
            for (int l = 0; l < 2; ++l) {
                int idx = t + l * 256;     // 0..511
                int r = idx >> 2, ch = idx & 3;
                int srcoff = r * 64 + (((ch + (r >> 1)) & 3) << 4);  // swizzled source
                int dstoff = r * DP_PITCH + ch * 16;                 // plain dest
                cp16(smA + dstoff, pA + (size_t)kt * 8192 + srcoff);
                cp16(smB + dstoff, pB + (size_t)kt * 8192 + srcoff);
            }
            CP_COMMIT();
            CP_WAIT(0);
            __syncthreads();

#pragma unroll
            for (int ch = 0; ch < 4; ++ch) {
                int4 a[4];
#pragma unroll
                for (int j = 0; j < 4; ++j)
                    a[j] = *(const int4*)(smc + (r0 + 32 * j) * DP_PITCH + ch * 16);
#pragma unroll
                for (int c = 0; c < 16; ++c) {
                    int4 b = *(const int4*)(smc + 10240 + (cg8 * 16 + c) * DP_PITCH + ch * 16);
#pragma unroll
                    for (int j = 0; j < 4; ++j) {
                        int s = acc[j][c];
                        s = __dp4a(a[j].x, b.x, s);
                        s = __dp4a(a[j].y, b.y, s);
                        s = __dp4a(a[j].z, b.z, s);
                        s = __dp4a(a[j].w, b.w, s);
                        acc[j][c] = s;
                    }
                }
            }
        }

        // epilogue: BN + sign, 16 cols/row -> STG.128 into swizzled panel
        const int gcol = col0 + cg8 * 16;
        int8_t* pnl = Aout + ((size_t)my * 16 + (gcol >> 6)) * 8192;
        const int cloc = gcol & 63;
        float sc[16], sh[16];
#pragma unroll
        for (int c = 0; c < 16; ++c) { sc[c] = s_scale[cg8 * 16 + c]; sh[c] = s_shift[cg8 * 16 + c]; }
#pragma unroll
        for (int j = 0; j < 4; ++j) {
            uint32_t w[4];
#pragma unroll
            for (int q = 0; q < 4; ++q) {
                uint32_t acc4 = 0;
#pragma unroll
                for (int k = 0; k < 4; ++k) {
                    int c = q * 4 + k;
                    float y = sc[c] * (float)acc[j][c] + sh[c];
                    acc4 |= (y >= 0.0f ? 0x01u : 0xFFu) << (8 * k);
                }
                w[q] = acc4;
            }
            *(int4*)(pnl + swz_off(r0 + 32 * j, cloc)) =
                make_int4((int)w[0], (int)w[1], (int)w[2], (int)w[3]);
        }
    }
}

// ===================== layer 4 via mma: N=16 (10 real), A in panels =====================
__global__ void __launch_bounds__(256)
final_mma(const int8_t* __restrict__ A, const int8_t* __restrict__ W,
          const float* __restrict__ bias, const float* __restrict__ gamma,
          const float* __restrict__ beta, const float* __restrict__ mean,
          const float* __restrict__ var, float* __restrict__ out) {
    const int lane = threadIdx.x & 31;
    const int wid  = threadIdx.x >> 5;
    const int row0 = (blockIdx.x * 8 + wid) * 16;
    const int mp   = row0 >> 7;
    const int rl0  = row0 & 127;

    int acc[2][4];
#pragma unroll
    for (int i = 0; i < 2; ++i)
#pragma unroll
        for (int k = 0; k < 4; ++k) acc[i][k] = 0;

    const int r4 = lane >> 2;
    const int c4 = (lane & 3) * 4;

#pragma unroll 4
    for (int ks = 0; ks < 32; ++ks) {
        int kb = ks * 32;
        const int8_t* pnl = A + ((size_t)mp * 16 + (kb >> 6)) * 8192;
        int cb = kb & 63;
        uint32_t a0 = *(const uint32_t*)(pnl + swz_off(rl0 + r4,     cb + c4));
        uint32_t a1 = *(const uint32_t*)(pnl + swz_off(rl0 + r4 + 8, cb + c4));
        uint32_t a2 = *(const uint32_t*)(pnl + swz_off(rl0 + r4,     cb + 16 + c4));
        uint32_t a3 = *(const uint32_t*)(pnl + swz_off(rl0 + r4 + 8, cb + 16 + c4));
#pragma unroll
        for (int nt = 0; nt < 2; ++nt) {
            uint32_t b0 = *(const uint32_t*)(W + (size_t)(nt * 8 + r4) * 1024 + kb + c4);
            uint32_t b1 = *(const uint32_t*)(W + (size_t)(nt * 8 + r4) * 1024 + kb + 16 + c4);
            MMA_S8(acc[nt], a0, a1, a2, a3, b0, b1);
        }
    }

#pragma unroll
    for (int nt = 0; nt < 2; ++nt)
#pragma unroll
        for (int k = 0; k < 4; ++k) {
            int c = nt * 8 + (lane & 3) * 2 + (k & 1);
            int r = row0 + (lane >> 2) + (k >> 1) * 8;
            if (c < 10) {
                float sv = gamma[c] * rsqrtf(var[c] + EPS_BN);
                out[(size_t)r * 10 + c] =
                    sv * ((float)acc[nt][k] + bias[c] - mean[c]) + beta[c];
            }
        }
}

// ===================== launch =====================
extern "C" void kernel_launch(void* const* d_in, const int* in_sizes, int n_in,
                              void* d_out, int out_size) {
    const float* x  = (const float*)d_in[0];
    const float* W1 = (const float*)d_in[1];
    const float* b1 = (const float*)d_in[2];
    const float* g1 = (const float*)d_in[3];
    const float* be1= (const float*)d_in[4];
    const float* m1 = (const float*)d_in[5];
    const float* v1 = (const float*)d_in[6];
    const float* W2 = (const float*)d_in[7];
    const float* b2 = (const float*)d_in[8];
    const float* g2 = (const float*)d_in[9];
    const float* be2= (const float*)d_in[10];
    const float* m2 = (const float*)d_in[11];
    const float* v2 = (const float*)d_in[12];
    const float* W3 = (const float*)d_in[13];
    const float* b3 = (const float*)d_in[14];
    const float* g3 = (const float*)d_in[15];
    const float* be3= (const float*)d_in[16];
    const float* m3 = (const float*)d_in[17];
    const float* v3 = (const float*)d_in[18];
    const float* W4 = (const float*)d_in[19];
    const float* b4 = (const float*)d_in[20];
    const float* g4 = (const float*)d_in[21];
    const float* be4= (const float*)d_in[22];
    const float* m4 = (const float*)d_in[23];
    const float* v4 = (const float*)d_in[24];

    int8_t *a0, *a1, *a2, *w1, *w2, *w3, *w4;
    cudaGetSymbolAddress((void**)&a0, g_A0);
    cudaGetSymbolAddress((void**)&a1, g_A1);
    cudaGetSymbolAddress((void**)&a2, g_A2);
    cudaGetSymbolAddress((void**)&w1, g_W1);
    cudaGetSymbolAddress((void**)&w2, g_W2);
    cudaGetSymbolAddress((void**)&w3, g_W3);
    cudaGetSymbolAddress((void**)&w4, g_W4);

    const int M = 32768;

    pack_all<<<3968, 256>>>(x, a0, W1, w1, W2, w2, W3, w3, W4, w4);

    cudaFuncSetAttribute(bgemm_split, cudaFuncAttributeMaxDynamicSharedMemorySize, SM_TOTAL);

    dim3 grid(8, 256);   // x = N tiles, y = M tiles; type scattered by linear bid

    bgemm_split<<<grid, 256, SM_TOTAL>>>(a0, w1, 14, b1, g1, be1, m1, v1, a1);
    bgemm_split<<<grid, 256, SM_TOTAL>>>(a1, w2, 16, b2, g2, be2, m2, v2, a2);
    bgemm_split<<<grid, 256, SM_TOTAL>>>(a2, w3, 16, b3, g3, be3, m3, v3, a1);

    final_mma<<<M / 128, 256>>>(a1, w4, b4, g4, be4, m4, v4, (float*)d_out);
}